// round 11
// baseline (speedup 1.0000x reference)
#include <cuda_runtime.h>
#include <math.h>

#define BB 8
#define PP 8192
#define FF 32
#define MM 2048
#define KK 64
#define NPTS (BB*PP)     // 65536
#define NC   (BB*MM)     // 16384
#define R2   0.04f

typedef unsigned long long ull;

// ------------ scratch (device globals; no allocation allowed) ------------
__device__ float g_a[NPTS*64];        // per-point layer1 pre-activation
__device__ float g_cent[NC*3];        // centroid coords (producer -> consumer)
__device__ volatile int g_prog[BB];   // #centroids published per cloud
__device__ float g_W2p[4096];         // W2 transposed to (j-pair, col, par)
__device__ float g_W3p[8192];         // W3 transposed to (j-pair, col, par)

// ---------------- packed f32x2 helpers (sm_103a) ----------------
__device__ __forceinline__ ull pk2(float lo, float hi) {
    ull r; asm("mov.b64 %0, {%1,%2};" : "=l"(r) : "f"(lo), "f"(hi)); return r;
}
__device__ __forceinline__ void upk2(ull v, float& lo, float& hi) {
    asm("mov.b64 {%0,%1}, %2;" : "=f"(lo), "=f"(hi) : "l"(v));
}
__device__ __forceinline__ ull add2(ull a, ull b) {
    ull r; asm("add.rn.f32x2 %0, %1, %2;" : "=l"(r) : "l"(a), "l"(b)); return r;
}
__device__ __forceinline__ ull mul2(ull a, ull b) {
    ull r; asm("mul.rn.f32x2 %0, %1, %2;" : "=l"(r) : "l"(a), "l"(b)); return r;
}
__device__ __forceinline__ void fma2(ull& acc, ull a, ull b) {
    asm("fma.rn.f32x2 %0, %1, %2, %0;" : "+l"(acc) : "l"(a), "l"(b));
}

// =========================================================================
// Kernel A: per-point layer-1 pre-activation
// =========================================================================
__global__ __launch_bounds__(256) void point_feat_kernel(const float* __restrict__ pos,
                                                         const float* __restrict__ x,
                                                         const float* __restrict__ W1,
                                                         const float* __restrict__ b1)
{
    int t = blockIdx.x * 256 + threadIdx.x;
    int j = t >> 6;
    int o = t & 63;
    const float* xr = x + (size_t)j * FF;
    const float* pr = pos + (size_t)j * 3;
    float acc = b1[o];
#pragma unroll
    for (int f = 0; f < FF; f++)
        acc = fmaf(__ldg(&xr[f]), __ldg(&W1[f*64 + o]), acc);
#pragma unroll
    for (int d = 0; d < 3; d++)
        acc = fmaf(__ldg(&pr[d]), __ldg(&W1[(FF+d)*64 + o]), acc);
    g_a[(size_t)j*64 + o] = acc;
}

// =========================================================================
// Kernel B: weight transpose + progress-flag reset (runs before fused kernel
// every launch, incl. graph replays -> deterministic start state)
// =========================================================================
__global__ __launch_bounds__(256) void wprep_kernel(const float* __restrict__ W2,
                                                    const float* __restrict__ W3)
{
    int t = blockIdx.x * 256 + threadIdx.x;
    if (t < BB) g_prog[t] = 0;
    if (t < 4096) {
        int j = t >> 6, c = t & 63;
        g_W2p[(((j >> 1) << 6) + c)*2 + (j & 1)] = W2[t];
    }
    if (t < 8192) {
        int j = t >> 7, c = t & 127;
        g_W3p[(((j >> 1) << 7) + c)*2 + (j & 1)] = W3[t];
    }
}

// =========================================================================
// Fused kernel: blocks 0..7 = FPS producers (one cloud each, 256 threads,
// 32 pts/thread, bit-exact packed rn distance arithmetic, atomicMin
// tie-break). Blocks 8.. = consumers (2 centroids each): spin on g_prog,
// ball query into smem (2 warps), then fused 2-layer MLP + masked max.
// =========================================================================
__global__ __launch_bounds__(256) void fused_kernel(const float* __restrict__ pos,
                                                    const float* __restrict__ W1,
                                                    const float* __restrict__ b2,
                                                    const float* __restrict__ b3,
                                                    float* __restrict__ out_cent,
                                                    float* __restrict__ outF,
                                                    float* __restrict__ outB)
{
    extern __shared__ float dynsm[];
    const int tid = threadIdx.x;
    const int lane = tid & 31;
    const int wid  = tid >> 5;

    if (blockIdx.x < BB) {
        // ================== PRODUCER: FPS ==================
        float* sx = dynsm;
        float* sy = dynsm + PP;
        float* sz = dynsm + 2*PP;
        __shared__ unsigned s_wd[2][8];
        __shared__ unsigned s_sel[2];

        const int b = blockIdx.x;
        const float* pb = pos + (size_t)b * PP * 3;

        float dist[32];
        ull px2[16], py2[16], pz2[16];
#pragma unroll
        for (int p = 0; p < 16; p++) {
            int i0 = (2*p) * 256 + tid;
            int i1 = (2*p+1) * 256 + tid;
            float x0 = pb[i0*3+0], y0 = pb[i0*3+1], z0 = pb[i0*3+2];
            float x1 = pb[i1*3+0], y1 = pb[i1*3+1], z1 = pb[i1*3+2];
            sx[i0] = x0; sy[i0] = y0; sz[i0] = z0;
            sx[i1] = x1; sy[i1] = y1; sz[i1] = z1;
            px2[p] = pk2(x0, x1); py2[p] = pk2(y0, y1); pz2[p] = pk2(z0, z1);
            dist[2*p] = INFINITY; dist[2*p+1] = INFINITY;
        }
        if (tid < 2) s_sel[tid] = 0xffffffffu;
        __syncthreads();

        float lx = sx[0], ly = sy[0], lz = sz[0];
        if (tid == 0) {
            int m0 = b * MM;
            g_cent[m0*3+0] = lx; g_cent[m0*3+1] = ly; g_cent[m0*3+2] = lz;
            out_cent[m0*3+0] = lx; out_cent[m0*3+1] = ly; out_cent[m0*3+2] = lz;
            __threadfence();
            g_prog[b] = 1;
        }

        for (int it = 1; it < MM; it++) {
            const int par = it & 1;
            const ull nlx2 = pk2(-lx, -lx);
            const ull nly2 = pk2(-ly, -ly);
            const ull nlz2 = pk2(-lz, -lz);
#pragma unroll
            for (int p = 0; p < 16; p++) {
                ull tx = add2(px2[p], nlx2); tx = mul2(tx, tx);   // rn(dx)^2
                ull ty = add2(py2[p], nly2); ty = mul2(ty, ty);
                ull s  = add2(tx, ty);                            // rn(dx2+dy2)
                ull tz = add2(pz2[p], nlz2); tz = mul2(tz, tz);
                s = add2(s, tz);                                  // + dz2
                float d0, d1; upk2(s, d0, d1);
                dist[2*p]   = fminf(dist[2*p],   d0);
                dist[2*p+1] = fminf(dist[2*p+1], d1);
            }
            // per-thread max via log-tree
            float mx[16];
#pragma unroll
            for (int p = 0; p < 16; p++) mx[p] = fmaxf(dist[2*p], dist[2*p+1]);
#pragma unroll
            for (int w = 8; w > 0; w >>= 1)
#pragma unroll
                for (int p = 0; p < w; p++) mx[p] = fmaxf(mx[p], mx[p+w]);
            float bd = mx[0];
            unsigned key  = __float_as_uint(bd);          // dists >= 0: monotonic
            unsigned wmax = __reduce_max_sync(0xffffffffu, key);
            if (lane == 0) s_wd[par][wid] = wmax;
            __syncthreads();
            unsigned gbits = __reduce_max_sync(0xffffffffu, s_wd[par][lane & 7]);
            if (tid == 0) s_sel[1 - par] = 0xffffffffu;   // reset slot for NEXT iter
            if (key == gbits) {                           // usually a single thread
                float gm = __uint_as_float(gbits);
                unsigned cand = 0xffffffffu;
#pragma unroll
                for (int u = 31; u >= 0; u--)
                    if (dist[u] == gm) cand = (unsigned)(u*256 + tid);
                atomicMin((unsigned*)&s_sel[par], cand);
            }
            __syncthreads();
            unsigned gi = s_sel[par];
            lx = sx[gi]; ly = sy[gi]; lz = sz[gi];
            if (tid == 0) {
                int mi = b * MM + it;
                g_cent[mi*3+0] = lx; g_cent[mi*3+1] = ly; g_cent[mi*3+2] = lz;
                out_cent[mi*3+0] = lx; out_cent[mi*3+1] = ly; out_cent[mi*3+2] = lz;
                __threadfence();
                g_prog[b] = it + 1;
            }
        }
        return;
    }

    // ================== CONSUMER: ball + MLP for 2 centroids ==================
    float* H1  = dynsm;            // 128 x 66
    float* H2  = H1 + 128*66;      // 128 x 66
    float* red = H1;               // reused after GEMM1 reads complete
    __shared__ float cw[128];
    __shared__ int   cnts[2];
    __shared__ int   snb[2][KK];
    __shared__ float scoord[2][3];

    const int m0 = (int)(blockIdx.x - BB) * 2;
    const int b  = m0 >> 11;
    const int li = m0 & (MM - 1);

    if (tid == 0) {
        while (g_prog[b] < li + 2) __nanosleep(256);
    }
    __syncthreads();
    __threadfence();

    // ---- ball query: warps 0,1 (centroid m0+wid), packed dists, smem out ----
    if (wid < 2) {
        const int mw = m0 + wid;
        const float* pb = pos + (size_t)b * PP * 3;
        float cx = __ldcv(&g_cent[mw*3+0]);
        float cy = __ldcv(&g_cent[mw*3+1]);
        float cz = __ldcv(&g_cent[mw*3+2]);
        const ull ncx2 = pk2(-cx, -cx);
        const ull ncy2 = pk2(-cy, -cy);
        const ull ncz2 = pk2(-cz, -cz);
        const unsigned lt = (1u << lane) - 1u;
        int cnt = 0;
        for (int base = 0; base < PP; base += 64) {
            int i0 = base + lane;
            int i1 = i0 + 32;
            float x0 = pb[i0*3+0], y0 = pb[i0*3+1], z0 = pb[i0*3+2];
            float x1 = pb[i1*3+0], y1 = pb[i1*3+1], z1 = pb[i1*3+2];
            ull tx = add2(pk2(x0, x1), ncx2); tx = mul2(tx, tx);
            ull ty = add2(pk2(y0, y1), ncy2); ty = mul2(ty, ty);
            ull s  = add2(tx, ty);
            ull tz = add2(pk2(z0, z1), ncz2); tz = mul2(tz, tz);
            s = add2(s, tz);
            float d0, d1; upk2(s, d0, d1);
            bool in0 = (d0 <= R2);
            bool in1 = (d1 <= R2);
            unsigned mk0 = __ballot_sync(0xffffffffu, in0);
            int slot0 = cnt + __popc(mk0 & lt);
            if (in0 && slot0 < KK) snb[wid][slot0] = i0;
            cnt += __popc(mk0);
            unsigned mk1 = __ballot_sync(0xffffffffu, in1);
            int slot1 = cnt + __popc(mk1 & lt);
            if (in1 && slot1 < KK) snb[wid][slot1] = i1;
            cnt += __popc(mk1);
            if (cnt >= KK) break;
        }
        if (lane == 0) {
            cnts[wid] = (cnt < KK) ? cnt : KK;
            scoord[wid][0] = cx; scoord[wid][1] = cy; scoord[wid][2] = cz;
        }
    }
    __syncthreads();

    // ---- cw = cent @ W1[32:35] per centroid ----
    if (tid < 128) {
        int ci = tid >> 6, o = tid & 63;
        float c0 = scoord[ci][0], c1 = scoord[ci][1], c2v = scoord[ci][2];
        cw[tid] = fmaf(c0, __ldg(&W1[2048+o]),
                  fmaf(c1, __ldg(&W1[2112+o]), c2v * __ldg(&W1[2176+o])));
    }
    __syncthreads();

    // ---- gather + layer1 elementwise: half a row per thread ----
    {
        int r = tid >> 1;                  // 0..127
        int seg = (tid & 1) * 32;
        int ci = r >> 6, k = r & 63;
        float* dst = H1 + r*66 + seg;
        if (k < cnts[ci]) {
            int j = b * PP + snb[ci][k];
            const float4* src = (const float4*)(g_a + (size_t)j*64 + seg);
#pragma unroll
            for (int q = 0; q < 8; q++) {
                float4 v = src[q];
                int o = seg + q*4;
                dst[q*4+0] = fmaxf(v.x - cw[ci*64+o+0], 0.f);
                dst[q*4+1] = fmaxf(v.y - cw[ci*64+o+1], 0.f);
                dst[q*4+2] = fmaxf(v.z - cw[ci*64+o+2], 0.f);
                dst[q*4+3] = fmaxf(v.w - cw[ci*64+o+3], 0.f);
            }
        } else {
#pragma unroll
            for (int q = 0; q < 32; q++) dst[q] = 0.f;
        }
    }
    __syncthreads();

    const int tx = tid & 7;
    const int ty = tid >> 3;              // 0..31, rows 4ty..4ty+3

    // ---- GEMM1: H2 = relu(H1 @ W2 + b2), 128x64, K=64 ----
    {
        ull acc[4][8];
#pragma unroll
        for (int i = 0; i < 4; i++)
#pragma unroll
            for (int c = 0; c < 8; c++) acc[i][c] = 0ull;
#pragma unroll 4
        for (int j2 = 0; j2 < 32; j2++) {
            ull a2[4];
#pragma unroll
            for (int i = 0; i < 4; i++)
                a2[i] = *(const ull*)&H1[(ty*4+i)*66 + 2*j2];
#pragma unroll
            for (int q = 0; q < 4; q++) {
                ulonglong2 w = __ldg((const ulonglong2*)&g_W2p[((j2 << 6) + 2*tx + 16*q)*2]);
#pragma unroll
                for (int i = 0; i < 4; i++) {
                    fma2(acc[i][2*q],   a2[i], w.x);
                    fma2(acc[i][2*q+1], a2[i], w.y);
                }
            }
        }
#pragma unroll
        for (int i = 0; i < 4; i++) {
#pragma unroll
            for (int q = 0; q < 4; q++) {
                int col = 2*tx + 16*q;
                float l0, h0, l1, h1;
                upk2(acc[i][2*q],   l0, h0);
                upk2(acc[i][2*q+1], l1, h1);
                float2 v;
                v.x = fmaxf(l0 + h0 + __ldg(&b2[col]),   0.f);
                v.y = fmaxf(l1 + h1 + __ldg(&b2[col+1]), 0.f);
                *(float2*)&H2[(ty*4+i)*66 + col] = v;
            }
        }
    }
    __syncthreads();

    // ---- GEMM2: H3 = relu(H2 @ W3 + b3), 2 column halves, fused max ----
    const int ci = ty >> 4;               // 0..1
    const int g  = ty & 15;               // row group within centroid
    const int cnt = cnts[ci];
#pragma unroll 1
    for (int h = 0; h < 2; h++) {
        ull acc[4][8];
#pragma unroll
        for (int i = 0; i < 4; i++)
#pragma unroll
            for (int c = 0; c < 8; c++) acc[i][c] = 0ull;
#pragma unroll 4
        for (int j2 = 0; j2 < 32; j2++) {
            ull a2[4];
#pragma unroll
            for (int i = 0; i < 4; i++)
                a2[i] = *(const ull*)&H2[(ty*4+i)*66 + 2*j2];
#pragma unroll
            for (int q = 0; q < 4; q++) {
                ulonglong2 w = __ldg((const ulonglong2*)&g_W3p[((j2 << 7) + h*64 + 2*tx + 16*q)*2]);
#pragma unroll
                for (int i = 0; i < 4; i++) {
                    fma2(acc[i][2*q],   a2[i], w.x);
                    fma2(acc[i][2*q+1], a2[i], w.y);
                }
            }
        }
        float pm[8];
#pragma unroll
        for (int c = 0; c < 8; c++) pm[c] = -3.402823466e38f;
#pragma unroll
        for (int i = 0; i < 4; i++) {
            int k = g*4 + i;
            if (k < cnt) {
#pragma unroll
                for (int q = 0; q < 4; q++) {
                    int col = 2*tx + 16*q;
                    float l0, h0v, l1, h1v;
                    upk2(acc[i][2*q],   l0, h0v);
                    upk2(acc[i][2*q+1], l1, h1v);
                    pm[2*q]   = fmaxf(pm[2*q],   fmaxf(l0 + h0v + __ldg(&b3[h*64+col]),   0.f));
                    pm[2*q+1] = fmaxf(pm[2*q+1], fmaxf(l1 + h1v + __ldg(&b3[h*64+col+1]), 0.f));
                }
            }
        }
#pragma unroll
        for (int q = 0; q < 4; q++) {
            int col = 2*tx + 16*q;
            float2 v; v.x = pm[2*q]; v.y = pm[2*q+1];
            *(float2*)&red[((h*2 + ci)*16 + g)*64 + col] = v;
        }
    }
    __syncthreads();

    // ---- final reduce over the 16 row-groups, write output ----
    {
        int cci = tid >> 7, col = tid & 127;
        int h = col >> 6, c64 = col & 63;
        float mmv = -3.402823466e38f;
#pragma unroll
        for (int gg = 0; gg < 16; gg++)
            mmv = fmaxf(mmv, red[((h*2 + cci)*16 + gg)*64 + c64]);
        outF[(size_t)(m0+cci)*128 + col] = mmv;
    }
    if (tid < 2) outB[m0 + tid] = (float)((m0 + tid) >> 11);
}

// =========================================================================
extern "C" void kernel_launch(void* const* d_in, const int* in_sizes, int n_in,
                              void* d_out, int out_size)
{
    const float* pos = (const float*)d_in[0];
    const float* x   = (const float*)d_in[2];
    const float* W1  = (const float*)d_in[3];
    const float* b1  = (const float*)d_in[4];
    const float* W2  = (const float*)d_in[5];
    const float* b2  = (const float*)d_in[6];
    const float* W3  = (const float*)d_in[7];
    const float* b3  = (const float*)d_in[8];

    float* out      = (float*)d_out;
    float* out_cent = out;
    float* out_feat = out + (size_t)NC*3;
    float* out_b    = out + (size_t)NC*3 + (size_t)NC*128;

    const int fused_smem = 3*PP*4;   // 98304 B (covers consumer's 67584 B too)
    cudaFuncSetAttribute(fused_kernel, cudaFuncAttributeMaxDynamicSharedMemorySize, fused_smem);

    point_feat_kernel<<<(NPTS*64)/256, 256>>>(pos, x, W1, b1);
    wprep_kernel<<<32, 256>>>(W2, W3);
    fused_kernel<<<BB + NC/2, 256, fused_smem>>>(pos, W1, b2, b3,
                                                 out_cent, out_feat, out_b);
}

// round 12
// speedup vs baseline: 1.2192x; 1.2192x over previous
#include <cuda_runtime.h>
#include <math.h>

#define BB 8
#define PP 8192
#define FF 32
#define MM 2048
#define KK 64
#define NPTS (BB*PP)     // 65536
#define NC   (BB*MM)     // 16384
#define R2   0.04f

typedef unsigned long long ull;

// ------------ scratch (device globals; no allocation allowed) ------------
__device__ float g_a[NPTS*64];        // per-point layer1 pre-activation
__device__ float g_cent[NC*3];        // centroid coords (producer -> consumer)
__device__ volatile int g_prog[BB];   // #centroids published per cloud
__device__ float g_W2p[4096];         // W2 transposed to (j-pair, col, par)
__device__ float g_W3p[8192];         // W3 transposed to (j-pair, col, par)

// ---------------- packed f32x2 helpers (sm_103a) ----------------
__device__ __forceinline__ ull pk2(float lo, float hi) {
    ull r; asm("mov.b64 %0, {%1,%2};" : "=l"(r) : "f"(lo), "f"(hi)); return r;
}
__device__ __forceinline__ void upk2(ull v, float& lo, float& hi) {
    asm("mov.b64 {%0,%1}, %2;" : "=f"(lo), "=f"(hi) : "l"(v));
}
__device__ __forceinline__ ull add2(ull a, ull b) {
    ull r; asm("add.rn.f32x2 %0, %1, %2;" : "=l"(r) : "l"(a), "l"(b)); return r;
}
__device__ __forceinline__ ull mul2(ull a, ull b) {
    ull r; asm("mul.rn.f32x2 %0, %1, %2;" : "=l"(r) : "l"(a), "l"(b)); return r;
}
__device__ __forceinline__ void fma2(ull& acc, ull a, ull b) {
    asm("fma.rn.f32x2 %0, %1, %2, %0;" : "+l"(acc) : "l"(a), "l"(b));
}

// =========================================================================
// Kernel A: per-point layer-1 pre-activation
// =========================================================================
__global__ __launch_bounds__(256) void point_feat_kernel(const float* __restrict__ pos,
                                                         const float* __restrict__ x,
                                                         const float* __restrict__ W1,
                                                         const float* __restrict__ b1)
{
    int t = blockIdx.x * 256 + threadIdx.x;
    int j = t >> 6;
    int o = t & 63;
    const float* xr = x + (size_t)j * FF;
    const float* pr = pos + (size_t)j * 3;
    float acc = b1[o];
#pragma unroll
    for (int f = 0; f < FF; f++)
        acc = fmaf(__ldg(&xr[f]), __ldg(&W1[f*64 + o]), acc);
#pragma unroll
    for (int d = 0; d < 3; d++)
        acc = fmaf(__ldg(&pr[d]), __ldg(&W1[(FF+d)*64 + o]), acc);
    g_a[(size_t)j*64 + o] = acc;
}

// =========================================================================
// Kernel B: weight transpose + progress-flag reset (every launch/replay)
// =========================================================================
__global__ __launch_bounds__(256) void wprep_kernel(const float* __restrict__ W2,
                                                    const float* __restrict__ W3)
{
    int t = blockIdx.x * 256 + threadIdx.x;
    if (t < BB) g_prog[t] = 0;
    if (t < 4096) {
        int j = t >> 6, c = t & 63;
        g_W2p[(((j >> 1) << 6) + c)*2 + (j & 1)] = W2[t];
    }
    if (t < 8192) {
        int j = t >> 7, c = t & 127;
        g_W3p[(((j >> 1) << 7) + c)*2 + (j & 1)] = W3[t];
    }
}

// =========================================================================
// Fused kernel (1024-thread blocks):
//   blocks 0..7   : FPS producer, one cloud each — identical hot loop to the
//                   proven R8 1024-thread kernel (8 pts/thread), publishing
//                   progress via g_cent + threadfence + g_prog.
//   blocks 8..    : consumer, 4 centroids each: spin on g_prog, ball query
//                   (4 warps), gather+L1, GEMM1, GEMM2+masked max, output.
// =========================================================================
__global__ __launch_bounds__(1024) void fused_kernel(const float* __restrict__ pos,
                                                     const float* __restrict__ W1,
                                                     const float* __restrict__ b2,
                                                     const float* __restrict__ b3,
                                                     float* __restrict__ out_cent,
                                                     float* __restrict__ outF,
                                                     float* __restrict__ outB)
{
    extern __shared__ float dynsm[];
    const int tid = threadIdx.x;
    const int lane = tid & 31;
    const int wid  = tid >> 5;

    if (blockIdx.x < BB) {
        // ================== PRODUCER: FPS (R8-identical hot loop) ==================
        float* sx = dynsm;
        float* sy = dynsm + PP;
        float* sz = dynsm + 2*PP;
        __shared__ unsigned s_wd[2][32];
        __shared__ unsigned s_sel[2];

        const int b = blockIdx.x;
        const float* pb = pos + (size_t)b * PP * 3;

        float pxs[8], pys[8], pzs[8], dist[8];
#pragma unroll
        for (int u = 0; u < 8; u++) {
            int i = u * 1024 + tid;
            float x = pb[i*3+0], y = pb[i*3+1], z = pb[i*3+2];
            pxs[u] = x; pys[u] = y; pzs[u] = z;
            sx[i] = x; sy[i] = y; sz[i] = z;
            dist[u] = INFINITY;
        }
        ull px2[4], py2[4], pz2[4];
#pragma unroll
        for (int p = 0; p < 4; p++) {
            px2[p] = pk2(pxs[2*p], pxs[2*p+1]);
            py2[p] = pk2(pys[2*p], pys[2*p+1]);
            pz2[p] = pk2(pzs[2*p], pzs[2*p+1]);
        }
        if (tid < 2) s_sel[tid] = 0xffffffffu;
        __syncthreads();

        float lx = sx[0], ly = sy[0], lz = sz[0];
        if (tid == 0) {
            int m0 = b * MM;
            g_cent[m0*3+0] = lx; g_cent[m0*3+1] = ly; g_cent[m0*3+2] = lz;
            out_cent[m0*3+0] = lx; out_cent[m0*3+1] = ly; out_cent[m0*3+2] = lz;
            __threadfence();
            g_prog[b] = 1;
        }

        for (int it = 1; it < MM; it++) {
            const int par = it & 1;
            const ull nlx2 = pk2(-lx, -lx);
            const ull nly2 = pk2(-ly, -ly);
            const ull nlz2 = pk2(-lz, -lz);
#pragma unroll
            for (int p = 0; p < 4; p++) {
                ull tx = add2(px2[p], nlx2); tx = mul2(tx, tx);   // rn(dx)^2
                ull ty = add2(py2[p], nly2); ty = mul2(ty, ty);
                ull s  = add2(tx, ty);                            // rn(dx2+dy2)
                ull tz = add2(pz2[p], nlz2); tz = mul2(tz, tz);
                s = add2(s, tz);                                  // + dz2
                float d0, d1; upk2(s, d0, d1);
                dist[2*p]   = fminf(dist[2*p],   d0);
                dist[2*p+1] = fminf(dist[2*p+1], d1);
            }
            float m0v = fmaxf(dist[0], dist[1]);
            float m1v = fmaxf(dist[2], dist[3]);
            float m2v = fmaxf(dist[4], dist[5]);
            float m3v = fmaxf(dist[6], dist[7]);
            float bd  = fmaxf(fmaxf(m0v, m1v), fmaxf(m2v, m3v));
            unsigned key  = __float_as_uint(bd);          // dists >= 0: monotonic
            unsigned wmax = __reduce_max_sync(0xffffffffu, key);
            if (lane == 0) s_wd[par][wid] = wmax;
            __syncthreads();
            unsigned gbits = __reduce_max_sync(0xffffffffu, s_wd[par][lane]);
            if (tid == 0) s_sel[1 - par] = 0xffffffffu;   // reset slot for NEXT iter
            if (key == gbits) {
                float gm = __uint_as_float(gbits);
                unsigned cand = 0xffffffffu;
#pragma unroll
                for (int u = 7; u >= 0; u--)
                    if (dist[u] == gm) cand = (unsigned)(u*1024 + tid);
                atomicMin((unsigned*)&s_sel[par], cand);
            }
            __syncthreads();
            unsigned gi = s_sel[par];
            lx = sx[gi]; ly = sy[gi]; lz = sz[gi];
            if (tid == 0) {
                int mi = b * MM + it;
                g_cent[mi*3+0] = lx; g_cent[mi*3+1] = ly; g_cent[mi*3+2] = lz;
                out_cent[mi*3+0] = lx; out_cent[mi*3+1] = ly; out_cent[mi*3+2] = lz;
                __threadfence();
                g_prog[b] = it + 1;
            }
        }
        return;
    }

    // ================== CONSUMER: ball + MLP for 4 centroids ==================
    float* H1  = dynsm;            // 256 x 66
    float* H2  = H1 + 256*66;      // 256 x 66
    float* red = H1;               // reused after GEMM1 (2*4*32*64 = 16384 <= 16896)
    __shared__ float cw[256];
    __shared__ int   cnts[4];
    __shared__ int   snb[4][KK];
    __shared__ float scoord[4][3];

    const int m0 = (int)(blockIdx.x - BB) * 4;
    const int b  = m0 >> 11;
    const int li = m0 & (MM - 1);

    if (tid == 0) {
        while (g_prog[b] < li + 4) __nanosleep(256);
    }
    __syncthreads();
    __threadfence();

    // ---- ball query: warps 0..3 (centroid m0+wid), packed dists, smem out ----
    if (wid < 4) {
        const int mw = m0 + wid;
        const float* pb = pos + (size_t)b * PP * 3;
        float cx = __ldcv(&g_cent[mw*3+0]);
        float cy = __ldcv(&g_cent[mw*3+1]);
        float cz = __ldcv(&g_cent[mw*3+2]);
        const ull ncx2 = pk2(-cx, -cx);
        const ull ncy2 = pk2(-cy, -cy);
        const ull ncz2 = pk2(-cz, -cz);
        const unsigned lt = (1u << lane) - 1u;
        int cnt = 0;
        for (int base = 0; base < PP; base += 64) {
            int i0 = base + lane;
            int i1 = i0 + 32;
            float x0 = pb[i0*3+0], y0 = pb[i0*3+1], z0 = pb[i0*3+2];
            float x1 = pb[i1*3+0], y1 = pb[i1*3+1], z1 = pb[i1*3+2];
            ull tx = add2(pk2(x0, x1), ncx2); tx = mul2(tx, tx);
            ull ty = add2(pk2(y0, y1), ncy2); ty = mul2(ty, ty);
            ull s  = add2(tx, ty);
            ull tz = add2(pk2(z0, z1), ncz2); tz = mul2(tz, tz);
            s = add2(s, tz);
            float d0, d1; upk2(s, d0, d1);
            bool in0 = (d0 <= R2);
            bool in1 = (d1 <= R2);
            unsigned mk0 = __ballot_sync(0xffffffffu, in0);
            int slot0 = cnt + __popc(mk0 & lt);
            if (in0 && slot0 < KK) snb[wid][slot0] = i0;
            cnt += __popc(mk0);
            unsigned mk1 = __ballot_sync(0xffffffffu, in1);
            int slot1 = cnt + __popc(mk1 & lt);
            if (in1 && slot1 < KK) snb[wid][slot1] = i1;
            cnt += __popc(mk1);
            if (cnt >= KK) break;
        }
        if (lane == 0) {
            cnts[wid] = (cnt < KK) ? cnt : KK;
            scoord[wid][0] = cx; scoord[wid][1] = cy; scoord[wid][2] = cz;
        }
    }
    __syncthreads();

    // ---- cw = cent @ W1[32:35] per centroid (4 x 64) ----
    if (tid < 256) {
        int ci = tid >> 6, o = tid & 63;
        float c0 = scoord[ci][0], c1 = scoord[ci][1], c2v = scoord[ci][2];
        cw[tid] = fmaf(c0, __ldg(&W1[2048+o]),
                  fmaf(c1, __ldg(&W1[2112+o]), c2v * __ldg(&W1[2176+o])));
    }
    __syncthreads();

    // ---- gather + layer1 elementwise: quarter row per thread ----
    {
        int r = tid >> 2;                  // 0..255
        int seg = (tid & 3) * 16;
        int ci = r >> 6, k = r & 63;
        float* dst = H1 + r*66 + seg;
        if (k < cnts[ci]) {
            int j = b * PP + snb[ci][k];
            const float4* src = (const float4*)(g_a + (size_t)j*64 + seg);
#pragma unroll
            for (int q = 0; q < 4; q++) {
                float4 v = src[q];
                int o = seg + q*4;
                dst[q*4+0] = fmaxf(v.x - cw[ci*64+o+0], 0.f);
                dst[q*4+1] = fmaxf(v.y - cw[ci*64+o+1], 0.f);
                dst[q*4+2] = fmaxf(v.z - cw[ci*64+o+2], 0.f);
                dst[q*4+3] = fmaxf(v.w - cw[ci*64+o+3], 0.f);
            }
        } else {
#pragma unroll
            for (int q = 0; q < 16; q++) dst[q] = 0.f;
        }
    }
    __syncthreads();

    const int tx = tid & 7;
    const int ty = tid >> 3;              // 0..127, rows 2ty..2ty+1

    // ---- GEMM1: H2 = relu(H1 @ W2 + b2), 256x64, K=64 ----
    {
        ull acc[2][8];
#pragma unroll
        for (int i = 0; i < 2; i++)
#pragma unroll
            for (int c = 0; c < 8; c++) acc[i][c] = 0ull;
#pragma unroll 4
        for (int j2 = 0; j2 < 32; j2++) {
            ull a2[2];
#pragma unroll
            for (int i = 0; i < 2; i++)
                a2[i] = *(const ull*)&H1[(ty*2+i)*66 + 2*j2];
#pragma unroll
            for (int q = 0; q < 4; q++) {
                ulonglong2 w = __ldg((const ulonglong2*)&g_W2p[((j2 << 6) + 2*tx + 16*q)*2]);
#pragma unroll
                for (int i = 0; i < 2; i++) {
                    fma2(acc[i][2*q],   a2[i], w.x);
                    fma2(acc[i][2*q+1], a2[i], w.y);
                }
            }
        }
#pragma unroll
        for (int i = 0; i < 2; i++) {
#pragma unroll
            for (int q = 0; q < 4; q++) {
                int col = 2*tx + 16*q;
                float l0, h0, l1, h1;
                upk2(acc[i][2*q],   l0, h0);
                upk2(acc[i][2*q+1], l1, h1);
                float2 v;
                v.x = fmaxf(l0 + h0 + __ldg(&b2[col]),   0.f);
                v.y = fmaxf(l1 + h1 + __ldg(&b2[col+1]), 0.f);
                *(float2*)&H2[(ty*2+i)*66 + col] = v;
            }
        }
    }
    __syncthreads();

    // ---- GEMM2: H3 = relu(H2 @ W3 + b3), 2 column halves, fused max ----
    const int ci = ty >> 5;               // 0..3
    const int g  = ty & 31;               // row pair within centroid
    const int cnt = cnts[ci];
#pragma unroll 1
    for (int h = 0; h < 2; h++) {
        ull acc[2][8];
#pragma unroll
        for (int i = 0; i < 2; i++)
#pragma unroll
            for (int c = 0; c < 8; c++) acc[i][c] = 0ull;
#pragma unroll 4
        for (int j2 = 0; j2 < 32; j2++) {
            ull a2[2];
#pragma unroll
            for (int i = 0; i < 2; i++)
                a2[i] = *(const ull*)&H2[(ty*2+i)*66 + 2*j2];
#pragma unroll
            for (int q = 0; q < 4; q++) {
                ulonglong2 w = __ldg((const ulonglong2*)&g_W3p[((j2 << 7) + h*64 + 2*tx + 16*q)*2]);
#pragma unroll
                for (int i = 0; i < 2; i++) {
                    fma2(acc[i][2*q],   a2[i], w.x);
                    fma2(acc[i][2*q+1], a2[i], w.y);
                }
            }
        }
        float pm[8];
#pragma unroll
        for (int c = 0; c < 8; c++) pm[c] = -3.402823466e38f;
#pragma unroll
        for (int i = 0; i < 2; i++) {
            int k = g*2 + i;
            if (k < cnt) {
#pragma unroll
                for (int q = 0; q < 4; q++) {
                    int col = 2*tx + 16*q;
                    float l0, h0v, l1, h1v;
                    upk2(acc[i][2*q],   l0, h0v);
                    upk2(acc[i][2*q+1], l1, h1v);
                    pm[2*q]   = fmaxf(pm[2*q],   fmaxf(l0 + h0v + __ldg(&b3[h*64+col]),   0.f));
                    pm[2*q+1] = fmaxf(pm[2*q+1], fmaxf(l1 + h1v + __ldg(&b3[h*64+col+1]), 0.f));
                }
            }
        }
#pragma unroll
        for (int q = 0; q < 4; q++) {
            int col = 2*tx + 16*q;
            float2 v; v.x = pm[2*q]; v.y = pm[2*q+1];
            *(float2*)&red[h*8192 + (ci*32 + g)*64 + col] = v;
        }
    }
    __syncthreads();

    // ---- final reduce over the 32 row-pair groups, write output ----
    if (tid < 512) {
        int cci = tid >> 7, col = tid & 127;
        int h = col >> 6, c64 = col & 63;
        float mmv = -3.402823466e38f;
#pragma unroll
        for (int gg = 0; gg < 32; gg++)
            mmv = fmaxf(mmv, red[h*8192 + (cci*32 + gg)*64 + c64]);
        outF[(size_t)(m0+cci)*128 + col] = mmv;
    }
    if (tid < 4) outB[m0 + tid] = (float)((m0 + tid) >> 11);
}

// =========================================================================
extern "C" void kernel_launch(void* const* d_in, const int* in_sizes, int n_in,
                              void* d_out, int out_size)
{
    const float* pos = (const float*)d_in[0];
    const float* x   = (const float*)d_in[2];
    const float* W1  = (const float*)d_in[3];
    const float* b1  = (const float*)d_in[4];
    const float* W2  = (const float*)d_in[5];
    const float* b2  = (const float*)d_in[6];
    const float* W3  = (const float*)d_in[7];
    const float* b3  = (const float*)d_in[8];

    float* out      = (float*)d_out;
    float* out_cent = out;
    float* out_feat = out + (size_t)NC*3;
    float* out_b    = out + (size_t)NC*3 + (size_t)NC*128;

    const int fused_smem = (2*256*66) * 4;   // 135168 B (>= FPS's 98304 B)
    cudaFuncSetAttribute(fused_kernel, cudaFuncAttributeMaxDynamicSharedMemorySize, fused_smem);

    point_feat_kernel<<<(NPTS*64)/256, 256>>>(pos, x, W1, b1);
    wprep_kernel<<<32, 256>>>(W2, W3);
    fused_kernel<<<BB + NC/4, 1024, fused_smem>>>(pos, W1, b2, b3,
                                                  out_cent, out_feat, out_b);
}

// round 13
// speedup vs baseline: 1.4476x; 1.1873x over previous
#include <cuda_runtime.h>
#include <math.h>

#define BB 8
#define PP 8192
#define FF 32
#define MM 2048
#define KK 64
#define NPTS (BB*PP)     // 65536
#define NC   (BB*MM)     // 16384
#define R2   0.04f
#define PUB  32          // progress publication period (divides MM)

typedef unsigned long long ull;

// ------------ scratch (device globals; no allocation allowed) ------------
__device__ float g_a[NPTS*64];        // per-point layer1 pre-activation
__device__ float g_cent[NC*3];        // centroid coords (producer -> consumer)
__device__ int   g_prog[BB];          // #centroids published per cloud
__device__ float g_W2p[4096];         // W2 transposed to (j-pair, col, par)
__device__ float g_W3p[8192];         // W3 transposed to (j-pair, col, par)

// ---------------- packed f32x2 helpers (sm_103a) ----------------
__device__ __forceinline__ ull pk2(float lo, float hi) {
    ull r; asm("mov.b64 %0, {%1,%2};" : "=l"(r) : "f"(lo), "f"(hi)); return r;
}
__device__ __forceinline__ void upk2(ull v, float& lo, float& hi) {
    asm("mov.b64 {%0,%1}, %2;" : "=f"(lo), "=f"(hi) : "l"(v));
}
__device__ __forceinline__ ull add2(ull a, ull b) {
    ull r; asm("add.rn.f32x2 %0, %1, %2;" : "=l"(r) : "l"(a), "l"(b)); return r;
}
__device__ __forceinline__ ull mul2(ull a, ull b) {
    ull r; asm("mul.rn.f32x2 %0, %1, %2;" : "=l"(r) : "l"(a), "l"(b)); return r;
}
__device__ __forceinline__ void fma2(ull& acc, ull a, ull b) {
    asm("fma.rn.f32x2 %0, %1, %2, %0;" : "+l"(acc) : "l"(a), "l"(b));
}
// ---------------- release/acquire progress channel ----------------
__device__ __forceinline__ void st_rel(int* p, int v) {
    asm volatile("st.release.gpu.s32 [%0], %1;" :: "l"(p), "r"(v) : "memory");
}
__device__ __forceinline__ int ld_acq(const int* p) {
    int v; asm volatile("ld.acquire.gpu.s32 %0, [%1];" : "=r"(v) : "l"(p) : "memory");
    return v;
}

// =========================================================================
// Kernel A: per-point layer-1 pre-activation
// =========================================================================
__global__ __launch_bounds__(256) void point_feat_kernel(const float* __restrict__ pos,
                                                         const float* __restrict__ x,
                                                         const float* __restrict__ W1,
                                                         const float* __restrict__ b1)
{
    int t = blockIdx.x * 256 + threadIdx.x;
    int j = t >> 6;
    int o = t & 63;
    const float* xr = x + (size_t)j * FF;
    const float* pr = pos + (size_t)j * 3;
    float acc = b1[o];
#pragma unroll
    for (int f = 0; f < FF; f++)
        acc = fmaf(__ldg(&xr[f]), __ldg(&W1[f*64 + o]), acc);
#pragma unroll
    for (int d = 0; d < 3; d++)
        acc = fmaf(__ldg(&pr[d]), __ldg(&W1[(FF+d)*64 + o]), acc);
    g_a[(size_t)j*64 + o] = acc;
}

// =========================================================================
// Kernel B: weight transpose + progress-flag reset (every launch/replay)
// =========================================================================
__global__ __launch_bounds__(256) void wprep_kernel(const float* __restrict__ W2,
                                                    const float* __restrict__ W3)
{
    int t = blockIdx.x * 256 + threadIdx.x;
    if (t < BB) g_prog[t] = 0;
    if (t < 4096) {
        int j = t >> 6, c = t & 63;
        g_W2p[(((j >> 1) << 6) + c)*2 + (j & 1)] = W2[t];
    }
    if (t < 8192) {
        int j = t >> 7, c = t & 127;
        g_W3p[(((j >> 1) << 7) + c)*2 + (j & 1)] = W3[t];
    }
}

// =========================================================================
// Fused kernel (1024-thread blocks):
//   blocks 0..7 : FPS producer (R8-identical hot loop; NO fence in loop —
//                 batched st.release.gpu publication every PUB iterations).
//   blocks 8..  : consumer, 4 centroids each: acquire-spin on g_prog, ball
//                 query (4 warps), gather+L1, GEMM1, GEMM2+masked max.
// =========================================================================
__global__ __launch_bounds__(1024) void fused_kernel(const float* __restrict__ pos,
                                                     const float* __restrict__ W1,
                                                     const float* __restrict__ b2,
                                                     const float* __restrict__ b3,
                                                     float* __restrict__ out_cent,
                                                     float* __restrict__ outF,
                                                     float* __restrict__ outB)
{
    extern __shared__ float dynsm[];
    const int tid = threadIdx.x;
    const int lane = tid & 31;
    const int wid  = tid >> 5;

    if (blockIdx.x < BB) {
        // ================== PRODUCER: FPS ==================
        float* sx = dynsm;
        float* sy = dynsm + PP;
        float* sz = dynsm + 2*PP;
        __shared__ unsigned s_wd[2][32];
        __shared__ unsigned s_sel[2];

        const int b = blockIdx.x;
        const float* pb = pos + (size_t)b * PP * 3;

        float pxs[8], pys[8], pzs[8], dist[8];
#pragma unroll
        for (int u = 0; u < 8; u++) {
            int i = u * 1024 + tid;
            float x = pb[i*3+0], y = pb[i*3+1], z = pb[i*3+2];
            pxs[u] = x; pys[u] = y; pzs[u] = z;
            sx[i] = x; sy[i] = y; sz[i] = z;
            dist[u] = INFINITY;
        }
        ull px2[4], py2[4], pz2[4];
#pragma unroll
        for (int p = 0; p < 4; p++) {
            px2[p] = pk2(pxs[2*p], pxs[2*p+1]);
            py2[p] = pk2(pys[2*p], pys[2*p+1]);
            pz2[p] = pk2(pzs[2*p], pzs[2*p+1]);
        }
        if (tid < 2) s_sel[tid] = 0xffffffffu;
        __syncthreads();

        float lx = sx[0], ly = sy[0], lz = sz[0];
        if (tid == 0) {
            int m0 = b * MM;
            g_cent[m0*3+0] = lx; g_cent[m0*3+1] = ly; g_cent[m0*3+2] = lz;
            out_cent[m0*3+0] = lx; out_cent[m0*3+1] = ly; out_cent[m0*3+2] = lz;
        }

        for (int it = 1; it < MM; it++) {
            const int par = it & 1;
            const ull nlx2 = pk2(-lx, -lx);
            const ull nly2 = pk2(-ly, -ly);
            const ull nlz2 = pk2(-lz, -lz);
#pragma unroll
            for (int p = 0; p < 4; p++) {
                ull tx = add2(px2[p], nlx2); tx = mul2(tx, tx);   // rn(dx)^2
                ull ty = add2(py2[p], nly2); ty = mul2(ty, ty);
                ull s  = add2(tx, ty);                            // rn(dx2+dy2)
                ull tz = add2(pz2[p], nlz2); tz = mul2(tz, tz);
                s = add2(s, tz);                                  // + dz2
                float d0, d1; upk2(s, d0, d1);
                dist[2*p]   = fminf(dist[2*p],   d0);
                dist[2*p+1] = fminf(dist[2*p+1], d1);
            }
            float m0v = fmaxf(dist[0], dist[1]);
            float m1v = fmaxf(dist[2], dist[3]);
            float m2v = fmaxf(dist[4], dist[5]);
            float m3v = fmaxf(dist[6], dist[7]);
            float bd  = fmaxf(fmaxf(m0v, m1v), fmaxf(m2v, m3v));
            unsigned key  = __float_as_uint(bd);          // dists >= 0: monotonic
            unsigned wmax = __reduce_max_sync(0xffffffffu, key);
            if (lane == 0) s_wd[par][wid] = wmax;
            __syncthreads();
            unsigned gbits = __reduce_max_sync(0xffffffffu, s_wd[par][lane]);
            if (tid == 0) s_sel[1 - par] = 0xffffffffu;   // reset slot for NEXT iter
            if (key == gbits) {
                float gm = __uint_as_float(gbits);
                unsigned cand = 0xffffffffu;
#pragma unroll
                for (int u = 7; u >= 0; u--)
                    if (dist[u] == gm) cand = (unsigned)(u*1024 + tid);
                atomicMin((unsigned*)&s_sel[par], cand);
            }
            __syncthreads();
            unsigned gi = s_sel[par];
            lx = sx[gi]; ly = sy[gi]; lz = sz[gi];
            if (tid == 0) {
                int mi = b * MM + it;
                g_cent[mi*3+0] = lx; g_cent[mi*3+1] = ly; g_cent[mi*3+2] = lz;
                out_cent[mi*3+0] = lx; out_cent[mi*3+1] = ly; out_cent[mi*3+2] = lz;
                if (((it + 1) & (PUB - 1)) == 0)
                    st_rel(&g_prog[b], it + 1);   // release: orders prior tid0 stores
            }
        }
        return;
    }

    // ================== CONSUMER: ball + MLP for 4 centroids ==================
    float* H1  = dynsm;            // 256 x 66
    float* H2  = H1 + 256*66;      // 256 x 66
    float* red = H1;               // reused after GEMM1 (16384 <= 16896)
    __shared__ float cw[256];
    __shared__ int   cnts[4];
    __shared__ int   snb[4][KK];
    __shared__ float scoord[4][3];

    const int m0 = (int)(blockIdx.x - BB) * 4;
    const int b  = m0 >> 11;
    const int li = m0 & (MM - 1);

    if (tid == 0) {
        while (ld_acq(&g_prog[b]) < li + 4) __nanosleep(256);
    }
    __syncthreads();

    // ---- ball query: warps 0..3 (centroid m0+wid), packed dists, smem out ----
    if (wid < 4) {
        const int mw = m0 + wid;
        const float* pb = pos + (size_t)b * PP * 3;
        float cx = __ldcv(&g_cent[mw*3+0]);
        float cy = __ldcv(&g_cent[mw*3+1]);
        float cz = __ldcv(&g_cent[mw*3+2]);
        const ull ncx2 = pk2(-cx, -cx);
        const ull ncy2 = pk2(-cy, -cy);
        const ull ncz2 = pk2(-cz, -cz);
        const unsigned lt = (1u << lane) - 1u;
        int cnt = 0;
        for (int base = 0; base < PP; base += 64) {
            int i0 = base + lane;
            int i1 = i0 + 32;
            float x0 = pb[i0*3+0], y0 = pb[i0*3+1], z0 = pb[i0*3+2];
            float x1 = pb[i1*3+0], y1 = pb[i1*3+1], z1 = pb[i1*3+2];
            ull tx = add2(pk2(x0, x1), ncx2); tx = mul2(tx, tx);
            ull ty = add2(pk2(y0, y1), ncy2); ty = mul2(ty, ty);
            ull s  = add2(tx, ty);
            ull tz = add2(pk2(z0, z1), ncz2); tz = mul2(tz, tz);
            s = add2(s, tz);
            float d0, d1; upk2(s, d0, d1);
            bool in0 = (d0 <= R2);
            bool in1 = (d1 <= R2);
            unsigned mk0 = __ballot_sync(0xffffffffu, in0);
            int slot0 = cnt + __popc(mk0 & lt);
            if (in0 && slot0 < KK) snb[wid][slot0] = i0;
            cnt += __popc(mk0);
            unsigned mk1 = __ballot_sync(0xffffffffu, in1);
            int slot1 = cnt + __popc(mk1 & lt);
            if (in1 && slot1 < KK) snb[wid][slot1] = i1;
            cnt += __popc(mk1);
            if (cnt >= KK) break;
        }
        if (lane == 0) {
            cnts[wid] = (cnt < KK) ? cnt : KK;
            scoord[wid][0] = cx; scoord[wid][1] = cy; scoord[wid][2] = cz;
        }
    }
    __syncthreads();

    // ---- cw = cent @ W1[32:35] per centroid (4 x 64) ----
    if (tid < 256) {
        int ci = tid >> 6, o = tid & 63;
        float c0 = scoord[ci][0], c1 = scoord[ci][1], c2v = scoord[ci][2];
        cw[tid] = fmaf(c0, __ldg(&W1[2048+o]),
                  fmaf(c1, __ldg(&W1[2112+o]), c2v * __ldg(&W1[2176+o])));
    }
    __syncthreads();

    // ---- gather + layer1 elementwise: quarter row per thread ----
    {
        int r = tid >> 2;                  // 0..255
        int seg = (tid & 3) * 16;
        int ci = r >> 6, k = r & 63;
        float* dst = H1 + r*66 + seg;
        if (k < cnts[ci]) {
            int j = b * PP + snb[ci][k];
            const float4* src = (const float4*)(g_a + (size_t)j*64 + seg);
#pragma unroll
            for (int q = 0; q < 4; q++) {
                float4 v = src[q];
                int o = seg + q*4;
                dst[q*4+0] = fmaxf(v.x - cw[ci*64+o+0], 0.f);
                dst[q*4+1] = fmaxf(v.y - cw[ci*64+o+1], 0.f);
                dst[q*4+2] = fmaxf(v.z - cw[ci*64+o+2], 0.f);
                dst[q*4+3] = fmaxf(v.w - cw[ci*64+o+3], 0.f);
            }
        } else {
#pragma unroll
            for (int q = 0; q < 16; q++) dst[q] = 0.f;
        }
    }
    __syncthreads();

    const int tx = tid & 7;
    const int ty = tid >> 3;              // 0..127, rows 2ty..2ty+1

    // ---- GEMM1: H2 = relu(H1 @ W2 + b2), 256x64, K=64 ----
    {
        ull acc[2][8];
#pragma unroll
        for (int i = 0; i < 2; i++)
#pragma unroll
            for (int c = 0; c < 8; c++) acc[i][c] = 0ull;
#pragma unroll 4
        for (int j2 = 0; j2 < 32; j2++) {
            ull a2[2];
#pragma unroll
            for (int i = 0; i < 2; i++)
                a2[i] = *(const ull*)&H1[(ty*2+i)*66 + 2*j2];
#pragma unroll
            for (int q = 0; q < 4; q++) {
                ulonglong2 w = __ldg((const ulonglong2*)&g_W2p[((j2 << 6) + 2*tx + 16*q)*2]);
#pragma unroll
                for (int i = 0; i < 2; i++) {
                    fma2(acc[i][2*q],   a2[i], w.x);
                    fma2(acc[i][2*q+1], a2[i], w.y);
                }
            }
        }
#pragma unroll
        for (int i = 0; i < 2; i++) {
#pragma unroll
            for (int q = 0; q < 4; q++) {
                int col = 2*tx + 16*q;
                float l0, h0, l1, h1;
                upk2(acc[i][2*q],   l0, h0);
                upk2(acc[i][2*q+1], l1, h1);
                float2 v;
                v.x = fmaxf(l0 + h0 + __ldg(&b2[col]),   0.f);
                v.y = fmaxf(l1 + h1 + __ldg(&b2[col+1]), 0.f);
                *(float2*)&H2[(ty*2+i)*66 + col] = v;
            }
        }
    }
    __syncthreads();

    // ---- GEMM2: H3 = relu(H2 @ W3 + b3), 2 column halves, fused max ----
    const int ci = ty >> 5;               // 0..3
    const int g  = ty & 31;               // row pair within centroid
    const int cnt = cnts[ci];
#pragma unroll 1
    for (int h = 0; h < 2; h++) {
        ull acc[2][8];
#pragma unroll
        for (int i = 0; i < 2; i++)
#pragma unroll
            for (int c = 0; c < 8; c++) acc[i][c] = 0ull;
#pragma unroll 4
        for (int j2 = 0; j2 < 32; j2++) {
            ull a2[2];
#pragma unroll
            for (int i = 0; i < 2; i++)
                a2[i] = *(const ull*)&H2[(ty*2+i)*66 + 2*j2];
#pragma unroll
            for (int q = 0; q < 4; q++) {
                ulonglong2 w = __ldg((const ulonglong2*)&g_W3p[((j2 << 7) + h*64 + 2*tx + 16*q)*2]);
#pragma unroll
                for (int i = 0; i < 2; i++) {
                    fma2(acc[i][2*q],   a2[i], w.x);
                    fma2(acc[i][2*q+1], a2[i], w.y);
                }
            }
        }
        float pm[8];
#pragma unroll
        for (int c = 0; c < 8; c++) pm[c] = -3.402823466e38f;
#pragma unroll
        for (int i = 0; i < 2; i++) {
            int k = g*2 + i;
            if (k < cnt) {
#pragma unroll
                for (int q = 0; q < 4; q++) {
                    int col = 2*tx + 16*q;
                    float l0, h0v, l1, h1v;
                    upk2(acc[i][2*q],   l0, h0v);
                    upk2(acc[i][2*q+1], l1, h1v);
                    pm[2*q]   = fmaxf(pm[2*q],   fmaxf(l0 + h0v + __ldg(&b3[h*64+col]),   0.f));
                    pm[2*q+1] = fmaxf(pm[2*q+1], fmaxf(l1 + h1v + __ldg(&b3[h*64+col+1]), 0.f));
                }
            }
        }
#pragma unroll
        for (int q = 0; q < 4; q++) {
            int col = 2*tx + 16*q;
            float2 v; v.x = pm[2*q]; v.y = pm[2*q+1];
            *(float2*)&red[h*8192 + (ci*32 + g)*64 + col] = v;
        }
    }
    __syncthreads();

    // ---- final reduce over the 32 row-pair groups, write output ----
    if (tid < 512) {
        int cci = tid >> 7, col = tid & 127;
        int h = col >> 6, c64 = col & 63;
        float mmv = -3.402823466e38f;
#pragma unroll
        for (int gg = 0; gg < 32; gg++)
            mmv = fmaxf(mmv, red[h*8192 + (cci*32 + gg)*64 + c64]);
        outF[(size_t)(m0+cci)*128 + col] = mmv;
    }
    if (tid < 4) outB[m0 + tid] = (float)((m0 + tid) >> 11);
}

// =========================================================================
extern "C" void kernel_launch(void* const* d_in, const int* in_sizes, int n_in,
                              void* d_out, int out_size)
{
    const float* pos = (const float*)d_in[0];
    const float* x   = (const float*)d_in[2];
    const float* W1  = (const float*)d_in[3];
    const float* b1  = (const float*)d_in[4];
    const float* W2  = (const float*)d_in[5];
    const float* b2  = (const float*)d_in[6];
    const float* W3  = (const float*)d_in[7];
    const float* b3  = (const float*)d_in[8];

    float* out      = (float*)d_out;
    float* out_cent = out;
    float* out_feat = out + (size_t)NC*3;
    float* out_b    = out + (size_t)NC*3 + (size_t)NC*128;

    const int fused_smem = (2*256*66) * 4;   // 135168 B (>= FPS's 98304 B)
    cudaFuncSetAttribute(fused_kernel, cudaFuncAttributeMaxDynamicSharedMemorySize, fused_smem);

    point_feat_kernel<<<(NPTS*64)/256, 256>>>(pos, x, W1, b1);
    wprep_kernel<<<32, 256>>>(W2, W3);
    fused_kernel<<<BB + NC/4, 1024, fused_smem>>>(pos, W1, b2, b3,
                                                  out_cent, out_feat, out_b);
}

// round 14
// speedup vs baseline: 2.0511x; 1.4169x over previous
#include <cuda_runtime.h>
#include <math.h>

#define BB 8
#define PP 8192
#define FF 32
#define MM 2048
#define KK 64
#define NPTS (BB*PP)     // 65536
#define NC   (BB*MM)     // 16384
#define R2   0.04f
#define PUB  32          // progress publication period (divides MM)

typedef unsigned long long ull;

// ------------ scratch (device globals; no allocation allowed) ------------
__device__ float g_a[NPTS*64];        // per-point layer1 pre-activation
__device__ float g_cent[NC*3];        // centroid coords (producer -> consumer)
__device__ int   g_prog[BB];          // #centroids published per cloud
__device__ float g_W2p[4096];         // W2 transposed to (j-pair, col, par)
__device__ float g_W3p[8192];         // W3 transposed to (j-pair, col, par)

// ---------------- packed f32x2 helpers (sm_103a) ----------------
__device__ __forceinline__ ull pk2(float lo, float hi) {
    ull r; asm("mov.b64 %0, {%1,%2};" : "=l"(r) : "f"(lo), "f"(hi)); return r;
}
__device__ __forceinline__ void upk2(ull v, float& lo, float& hi) {
    asm("mov.b64 {%0,%1}, %2;" : "=f"(lo), "=f"(hi) : "l"(v));
}
__device__ __forceinline__ ull add2(ull a, ull b) {
    ull r; asm("add.rn.f32x2 %0, %1, %2;" : "=l"(r) : "l"(a), "l"(b)); return r;
}
__device__ __forceinline__ ull mul2(ull a, ull b) {
    ull r; asm("mul.rn.f32x2 %0, %1, %2;" : "=l"(r) : "l"(a), "l"(b)); return r;
}
__device__ __forceinline__ void fma2(ull& acc, ull a, ull b) {
    asm("fma.rn.f32x2 %0, %1, %2, %0;" : "+l"(acc) : "l"(a), "l"(b));
}
// ---------------- release/acquire progress channel ----------------
__device__ __forceinline__ void st_rel(int* p, int v) {
    asm volatile("st.release.gpu.s32 [%0], %1;" :: "l"(p), "r"(v) : "memory");
}
__device__ __forceinline__ int ld_acq(const int* p) {
    int v; asm volatile("ld.acquire.gpu.s32 %0, [%1];" : "=r"(v) : "l"(p) : "memory");
    return v;
}

// =========================================================================
// Kernel A: per-point layer-1 pre-activation
// =========================================================================
__global__ __launch_bounds__(256) void point_feat_kernel(const float* __restrict__ pos,
                                                         const float* __restrict__ x,
                                                         const float* __restrict__ W1,
                                                         const float* __restrict__ b1)
{
    int t = blockIdx.x * 256 + threadIdx.x;
    int j = t >> 6;
    int o = t & 63;
    const float* xr = x + (size_t)j * FF;
    const float* pr = pos + (size_t)j * 3;
    float acc = b1[o];
#pragma unroll
    for (int f = 0; f < FF; f++)
        acc = fmaf(__ldg(&xr[f]), __ldg(&W1[f*64 + o]), acc);
#pragma unroll
    for (int d = 0; d < 3; d++)
        acc = fmaf(__ldg(&pr[d]), __ldg(&W1[(FF+d)*64 + o]), acc);
    g_a[(size_t)j*64 + o] = acc;
}

// =========================================================================
// Kernel B: weight transpose + progress-flag reset (every launch/replay)
// =========================================================================
__global__ __launch_bounds__(256) void wprep_kernel(const float* __restrict__ W2,
                                                    const float* __restrict__ W3)
{
    int t = blockIdx.x * 256 + threadIdx.x;
    if (t < BB) g_prog[t] = 0;
    if (t < 4096) {
        int j = t >> 6, c = t & 63;
        g_W2p[(((j >> 1) << 6) + c)*2 + (j & 1)] = W2[t];
    }
    if (t < 8192) {
        int j = t >> 7, c = t & 127;
        g_W3p[(((j >> 1) << 7) + c)*2 + (j & 1)] = W3[t];
    }
}

// =========================================================================
// Fused kernel (1024-thread blocks):
//   blocks 0..7 : FPS producer (R8-identical hot loop; batched
//                 st.release.gpu publication every PUB iterations).
//   blocks 8..  : consumer, 4 centroids each, INTERLEAVED across clouds:
//                 n = bid-8 -> cloud = n&7, li = (n>>3)*4. Resident
//                 consumers cover all 8 producers concurrently.
// =========================================================================
__global__ __launch_bounds__(1024) void fused_kernel(const float* __restrict__ pos,
                                                     const float* __restrict__ W1,
                                                     const float* __restrict__ b2,
                                                     const float* __restrict__ b3,
                                                     float* __restrict__ out_cent,
                                                     float* __restrict__ outF,
                                                     float* __restrict__ outB)
{
    extern __shared__ float dynsm[];
    const int tid = threadIdx.x;
    const int lane = tid & 31;
    const int wid  = tid >> 5;

    if (blockIdx.x < BB) {
        // ================== PRODUCER: FPS ==================
        float* sx = dynsm;
        float* sy = dynsm + PP;
        float* sz = dynsm + 2*PP;
        __shared__ unsigned s_wd[2][32];
        __shared__ unsigned s_sel[2];

        const int b = blockIdx.x;
        const float* pb = pos + (size_t)b * PP * 3;

        float pxs[8], pys[8], pzs[8], dist[8];
#pragma unroll
        for (int u = 0; u < 8; u++) {
            int i = u * 1024 + tid;
            float x = pb[i*3+0], y = pb[i*3+1], z = pb[i*3+2];
            pxs[u] = x; pys[u] = y; pzs[u] = z;
            sx[i] = x; sy[i] = y; sz[i] = z;
            dist[u] = INFINITY;
        }
        ull px2[4], py2[4], pz2[4];
#pragma unroll
        for (int p = 0; p < 4; p++) {
            px2[p] = pk2(pxs[2*p], pxs[2*p+1]);
            py2[p] = pk2(pys[2*p], pys[2*p+1]);
            pz2[p] = pk2(pzs[2*p], pzs[2*p+1]);
        }
        if (tid < 2) s_sel[tid] = 0xffffffffu;
        __syncthreads();

        float lx = sx[0], ly = sy[0], lz = sz[0];
        if (tid == 0) {
            int m0 = b * MM;
            g_cent[m0*3+0] = lx; g_cent[m0*3+1] = ly; g_cent[m0*3+2] = lz;
            out_cent[m0*3+0] = lx; out_cent[m0*3+1] = ly; out_cent[m0*3+2] = lz;
        }

        for (int it = 1; it < MM; it++) {
            const int par = it & 1;
            const ull nlx2 = pk2(-lx, -lx);
            const ull nly2 = pk2(-ly, -ly);
            const ull nlz2 = pk2(-lz, -lz);
#pragma unroll
            for (int p = 0; p < 4; p++) {
                ull tx = add2(px2[p], nlx2); tx = mul2(tx, tx);   // rn(dx)^2
                ull ty = add2(py2[p], nly2); ty = mul2(ty, ty);
                ull s  = add2(tx, ty);                            // rn(dx2+dy2)
                ull tz = add2(pz2[p], nlz2); tz = mul2(tz, tz);
                s = add2(s, tz);                                  // + dz2
                float d0, d1; upk2(s, d0, d1);
                dist[2*p]   = fminf(dist[2*p],   d0);
                dist[2*p+1] = fminf(dist[2*p+1], d1);
            }
            float m0v = fmaxf(dist[0], dist[1]);
            float m1v = fmaxf(dist[2], dist[3]);
            float m2v = fmaxf(dist[4], dist[5]);
            float m3v = fmaxf(dist[6], dist[7]);
            float bd  = fmaxf(fmaxf(m0v, m1v), fmaxf(m2v, m3v));
            unsigned key  = __float_as_uint(bd);          // dists >= 0: monotonic
            unsigned wmax = __reduce_max_sync(0xffffffffu, key);
            if (lane == 0) s_wd[par][wid] = wmax;
            __syncthreads();
            unsigned gbits = __reduce_max_sync(0xffffffffu, s_wd[par][lane]);
            if (tid == 0) s_sel[1 - par] = 0xffffffffu;   // reset slot for NEXT iter
            if (key == gbits) {
                float gm = __uint_as_float(gbits);
                unsigned cand = 0xffffffffu;
#pragma unroll
                for (int u = 7; u >= 0; u--)
                    if (dist[u] == gm) cand = (unsigned)(u*1024 + tid);
                atomicMin((unsigned*)&s_sel[par], cand);
            }
            __syncthreads();
            unsigned gi = s_sel[par];
            lx = sx[gi]; ly = sy[gi]; lz = sz[gi];
            if (tid == 0) {
                int mi = b * MM + it;
                g_cent[mi*3+0] = lx; g_cent[mi*3+1] = ly; g_cent[mi*3+2] = lz;
                out_cent[mi*3+0] = lx; out_cent[mi*3+1] = ly; out_cent[mi*3+2] = lz;
                if (((it + 1) & (PUB - 1)) == 0)
                    st_rel(&g_prog[b], it + 1);   // release: orders prior tid0 stores
            }
        }
        return;
    }

    // ================== CONSUMER: ball + MLP for 4 centroids ==================
    float* H1  = dynsm;            // 256 x 66
    float* H2  = H1 + 256*66;      // 256 x 66
    float* red = H1;               // reused after GEMM1 (16384 <= 16896)
    __shared__ float cw[256];
    __shared__ int   cnts[4];
    __shared__ int   snb[4][KK];
    __shared__ float scoord[4][3];

    // interleaved mapping: consecutive blocks cover all 8 clouds at same li
    const int n  = (int)(blockIdx.x - BB);
    const int b  = n & 7;
    const int li = (n >> 3) * 4;
    const int m0 = b * MM + li;

    if (tid == 0) {
        while (ld_acq(&g_prog[b]) < li + 4) __nanosleep(256);
    }
    __syncthreads();

    // ---- ball query: warps 0..3 (centroid m0+wid), packed dists, smem out ----
    if (wid < 4) {
        const int mw = m0 + wid;
        const float* pb = pos + (size_t)b * PP * 3;
        float cx = __ldcv(&g_cent[mw*3+0]);
        float cy = __ldcv(&g_cent[mw*3+1]);
        float cz = __ldcv(&g_cent[mw*3+2]);
        const ull ncx2 = pk2(-cx, -cx);
        const ull ncy2 = pk2(-cy, -cy);
        const ull ncz2 = pk2(-cz, -cz);
        const unsigned lt = (1u << lane) - 1u;
        int cnt = 0;
        for (int base = 0; base < PP; base += 64) {
            int i0 = base + lane;
            int i1 = i0 + 32;
            float x0 = pb[i0*3+0], y0 = pb[i0*3+1], z0 = pb[i0*3+2];
            float x1 = pb[i1*3+0], y1 = pb[i1*3+1], z1 = pb[i1*3+2];
            ull tx = add2(pk2(x0, x1), ncx2); tx = mul2(tx, tx);
            ull ty = add2(pk2(y0, y1), ncy2); ty = mul2(ty, ty);
            ull s  = add2(tx, ty);
            ull tz = add2(pk2(z0, z1), ncz2); tz = mul2(tz, tz);
            s = add2(s, tz);
            float d0, d1; upk2(s, d0, d1);
            bool in0 = (d0 <= R2);
            bool in1 = (d1 <= R2);
            unsigned mk0 = __ballot_sync(0xffffffffu, in0);
            int slot0 = cnt + __popc(mk0 & lt);
            if (in0 && slot0 < KK) snb[wid][slot0] = i0;
            cnt += __popc(mk0);
            unsigned mk1 = __ballot_sync(0xffffffffu, in1);
            int slot1 = cnt + __popc(mk1 & lt);
            if (in1 && slot1 < KK) snb[wid][slot1] = i1;
            cnt += __popc(mk1);
            if (cnt >= KK) break;
        }
        if (lane == 0) {
            cnts[wid] = (cnt < KK) ? cnt : KK;
            scoord[wid][0] = cx; scoord[wid][1] = cy; scoord[wid][2] = cz;
        }
    }
    __syncthreads();

    // ---- cw = cent @ W1[32:35] per centroid (4 x 64) ----
    if (tid < 256) {
        int ci = tid >> 6, o = tid & 63;
        float c0 = scoord[ci][0], c1 = scoord[ci][1], c2v = scoord[ci][2];
        cw[tid] = fmaf(c0, __ldg(&W1[2048+o]),
                  fmaf(c1, __ldg(&W1[2112+o]), c2v * __ldg(&W1[2176+o])));
    }
    __syncthreads();

    // ---- gather + layer1 elementwise: quarter row per thread ----
    {
        int r = tid >> 2;                  // 0..255
        int seg = (tid & 3) * 16;
        int ci = r >> 6, k = r & 63;
        float* dst = H1 + r*66 + seg;
        if (k < cnts[ci]) {
            int j = b * PP + snb[ci][k];
            const float4* src = (const float4*)(g_a + (size_t)j*64 + seg);
#pragma unroll
            for (int q = 0; q < 4; q++) {
                float4 v = src[q];
                int o = seg + q*4;
                dst[q*4+0] = fmaxf(v.x - cw[ci*64+o+0], 0.f);
                dst[q*4+1] = fmaxf(v.y - cw[ci*64+o+1], 0.f);
                dst[q*4+2] = fmaxf(v.z - cw[ci*64+o+2], 0.f);
                dst[q*4+3] = fmaxf(v.w - cw[ci*64+o+3], 0.f);
            }
        } else {
#pragma unroll
            for (int q = 0; q < 16; q++) dst[q] = 0.f;
        }
    }
    __syncthreads();

    const int tx = tid & 7;
    const int ty = tid >> 3;              // 0..127, rows 2ty..2ty+1

    // ---- GEMM1: H2 = relu(H1 @ W2 + b2), 256x64, K=64 ----
    {
        ull acc[2][8];
#pragma unroll
        for (int i = 0; i < 2; i++)
#pragma unroll
            for (int c = 0; c < 8; c++) acc[i][c] = 0ull;
#pragma unroll 4
        for (int j2 = 0; j2 < 32; j2++) {
            ull a2[2];
#pragma unroll
            for (int i = 0; i < 2; i++)
                a2[i] = *(const ull*)&H1[(ty*2+i)*66 + 2*j2];
#pragma unroll
            for (int q = 0; q < 4; q++) {
                ulonglong2 w = __ldg((const ulonglong2*)&g_W2p[((j2 << 6) + 2*tx + 16*q)*2]);
#pragma unroll
                for (int i = 0; i < 2; i++) {
                    fma2(acc[i][2*q],   a2[i], w.x);
                    fma2(acc[i][2*q+1], a2[i], w.y);
                }
            }
        }
#pragma unroll
        for (int i = 0; i < 2; i++) {
#pragma unroll
            for (int q = 0; q < 4; q++) {
                int col = 2*tx + 16*q;
                float l0, h0, l1, h1;
                upk2(acc[i][2*q],   l0, h0);
                upk2(acc[i][2*q+1], l1, h1);
                float2 v;
                v.x = fmaxf(l0 + h0 + __ldg(&b2[col]),   0.f);
                v.y = fmaxf(l1 + h1 + __ldg(&b2[col+1]), 0.f);
                *(float2*)&H2[(ty*2+i)*66 + col] = v;
            }
        }
    }
    __syncthreads();

    // ---- GEMM2: H3 = relu(H2 @ W3 + b3), 2 column halves, fused max ----
    const int ci = ty >> 5;               // 0..3
    const int g  = ty & 31;               // row pair within centroid
    const int cnt = cnts[ci];
#pragma unroll 1
    for (int h = 0; h < 2; h++) {
        ull acc[2][8];
#pragma unroll
        for (int i = 0; i < 2; i++)
#pragma unroll
            for (int c = 0; c < 8; c++) acc[i][c] = 0ull;
#pragma unroll 4
        for (int j2 = 0; j2 < 32; j2++) {
            ull a2[2];
#pragma unroll
            for (int i = 0; i < 2; i++)
                a2[i] = *(const ull*)&H2[(ty*2+i)*66 + 2*j2];
#pragma unroll
            for (int q = 0; q < 4; q++) {
                ulonglong2 w = __ldg((const ulonglong2*)&g_W3p[((j2 << 7) + h*64 + 2*tx + 16*q)*2]);
#pragma unroll
                for (int i = 0; i < 2; i++) {
                    fma2(acc[i][2*q],   a2[i], w.x);
                    fma2(acc[i][2*q+1], a2[i], w.y);
                }
            }
        }
        float pm[8];
#pragma unroll
        for (int c = 0; c < 8; c++) pm[c] = -3.402823466e38f;
#pragma unroll
        for (int i = 0; i < 2; i++) {
            int k = g*2 + i;
            if (k < cnt) {
#pragma unroll
                for (int q = 0; q < 4; q++) {
                    int col = 2*tx + 16*q;
                    float l0, h0v, l1, h1v;
                    upk2(acc[i][2*q],   l0, h0v);
                    upk2(acc[i][2*q+1], l1, h1v);
                    pm[2*q]   = fmaxf(pm[2*q],   fmaxf(l0 + h0v + __ldg(&b3[h*64+col]),   0.f));
                    pm[2*q+1] = fmaxf(pm[2*q+1], fmaxf(l1 + h1v + __ldg(&b3[h*64+col+1]), 0.f));
                }
            }
        }
#pragma unroll
        for (int q = 0; q < 4; q++) {
            int col = 2*tx + 16*q;
            float2 v; v.x = pm[2*q]; v.y = pm[2*q+1];
            *(float2*)&red[h*8192 + (ci*32 + g)*64 + col] = v;
        }
    }
    __syncthreads();

    // ---- final reduce over the 32 row-pair groups, write output ----
    if (tid < 512) {
        int cci = tid >> 7, col = tid & 127;
        int h = col >> 6, c64 = col & 63;
        float mmv = -3.402823466e38f;
#pragma unroll
        for (int gg = 0; gg < 32; gg++)
            mmv = fmaxf(mmv, red[h*8192 + (cci*32 + gg)*64 + c64]);
        outF[(size_t)(m0+cci)*128 + col] = mmv;
    }
    if (tid < 4) outB[m0 + tid] = (float)b;
}

// =========================================================================
extern "C" void kernel_launch(void* const* d_in, const int* in_sizes, int n_in,
                              void* d_out, int out_size)
{
    const float* pos = (const float*)d_in[0];
    const float* x   = (const float*)d_in[2];
    const float* W1  = (const float*)d_in[3];
    const float* b1  = (const float*)d_in[4];
    const float* W2  = (const float*)d_in[5];
    const float* b2  = (const float*)d_in[6];
    const float* W3  = (const float*)d_in[7];
    const float* b3  = (const float*)d_in[8];

    float* out      = (float*)d_out;
    float* out_cent = out;
    float* out_feat = out + (size_t)NC*3;
    float* out_b    = out + (size_t)NC*3 + (size_t)NC*128;

    const int fused_smem = (2*256*66) * 4;   // 135168 B (>= FPS's 98304 B)
    cudaFuncSetAttribute(fused_kernel, cudaFuncAttributeMaxDynamicSharedMemorySize, fused_smem);

    point_feat_kernel<<<(NPTS*64)/256, 256>>>(pos, x, W1, b1);
    wprep_kernel<<<32, 256>>>(W2, W3);
    fused_kernel<<<BB + NC/4, 1024, fused_smem>>>(pos, W1, b2, b3,
                                                  out_cent, out_feat, out_b);
}